// round 3
// baseline (speedup 1.0000x reference)
#include <cuda_runtime.h>
#include <math.h>

#define NN 20000
#define EE 50000
#define BB 128
#define HH 64
#define FEATD 28
#define NTYPES 100
#define MPI 3
#define S2SI 4

// ---------------- scratch (no allocations allowed) ----------------
__device__ __align__(16) float g_W5[5 * HH * HH];   // 5 edge matrices [t][h_in][h_out]
__device__ __align__(16) float g_h0[NN * HH];
__device__ __align__(16) float g_h1[NN * HH];
__device__ float g_e[NN];
__device__ int   g_off[BB + 1];
__device__ __align__(16) float g_hx[BB * HH];
__device__ __align__(16) float g_cx[BB * HH];
__device__ __align__(16) float g_qstar[BB * 2 * HH];

// ---------------- edge matrices: W_t = relu(W_e1[t]+b_e1) @ W_e2 + b_e2 ----------------
__global__ void k_edgemats(const float* __restrict__ We1, const float* __restrict__ be1,
                           const float* __restrict__ We2, const float* __restrict__ be2) {
    int t = blockIdx.y;
    int j = blockIdx.x * 256 + threadIdx.x;   // 0..4095
    __shared__ float relu_s[64];
    if (threadIdx.x < 64) {
        float v = We1[t * 64 + threadIdx.x] + be1[threadIdx.x];
        relu_s[threadIdx.x] = v > 0.f ? v : 0.f;
    }
    __syncthreads();
    float acc = be2[j];
#pragma unroll 8
    for (int m = 0; m < 64; m++)
        acc = fmaf(relu_s[m], We2[m * 4096 + j], acc);
    g_W5[t * 4096 + j] = acc;
}

// ---------------- node embedding ----------------
__global__ void k_embed(const float* __restrict__ feat, const int* __restrict__ ntype,
                        const float* __restrict__ W_emb, const float* __restrict__ b_emb,
                        float* __restrict__ h) {
    int idx = blockIdx.x * 256 + threadIdx.x;   // N*64 threads exactly
    int n = idx >> 6, o = idx & 63;
    int t = ntype[n];
    float acc = W_emb[t * 64 + o] + b_emb[o];
#pragma unroll
    for (int f = 0; f < FEATD; f++)
        acc = fmaf(feat[n * FEATD + f], W_emb[(NTYPES + f) * 64 + o], acc);
    h[idx] = acc;
}

// ---------------- init: graph offsets (batch sorted) + zero LSTM state ----------------
__global__ void k_init(const int* __restrict__ batch) {
    int tid = blockIdx.x * blockDim.x + threadIdx.x;
    if (tid < BB * HH) { g_hx[tid] = 0.f; g_cx[tid] = 0.f; }
    if (tid < BB * 2 * HH) g_qstar[tid] = 0.f;
    if (tid <= BB) {
        int lo = 0, hi = NN;
        while (lo < hi) {
            int mid = (lo + hi) >> 1;
            if (batch[mid] < tid) lo = mid + 1; else hi = mid;
        }
        g_off[tid] = lo;
    }
}

// ---------------- root transform: h_out = h_in @ root + bias ----------------
__global__ void k_root(const float* __restrict__ h_in, const float* __restrict__ root,
                       const float* __restrict__ bias, float* __restrict__ h_out) {
    __shared__ float root_s[64 * 64];
    __shared__ float h_s[8 * 64];
    int tid = threadIdx.x;
#pragma unroll
    for (int i = 0; i < 16; i++) root_s[i * 256 + tid] = root[i * 256 + tid];
    int n0 = blockIdx.x * 8;                    // 2500 blocks * 8 = 20000, exact
    h_s[tid]       = h_in[n0 * 64 + tid];
    h_s[256 + tid] = h_in[n0 * 64 + 256 + tid];
    __syncthreads();
    int ohalf = tid & 31, nl = tid >> 5;
    const float2* r2 = (const float2*)root_s;
    const float* hr = h_s + nl * 64;
    float2 acc;
    acc.x = bias[2 * ohalf]; acc.y = bias[2 * ohalf + 1];
#pragma unroll 16
    for (int k = 0; k < 64; k++) {
        float hk = hr[k];
        float2 w = r2[k * 32 + ohalf];
        acc.x = fmaf(hk, w.x, acc.x);
        acc.y = fmaf(hk, w.y, acc.y);
    }
    ((float2*)h_out)[(n0 + nl) * 32 + ohalf] = acc;
}

// ---------------- edge scatter: h_out[dst] += h_in[src] @ W_{etype} ----------------
__global__ void k_edge(const float* __restrict__ h_in, const int* __restrict__ edge_index,
                       const int* __restrict__ etype, float* __restrict__ h_out) {
    extern __shared__ float Wsh[];   // 5*4096 floats = 80KB
    int tid = threadIdx.x;
    for (int i = tid; i < 5 * 4096; i += 256) Wsh[i] = g_W5[i];
    __syncthreads();
    int lane = tid & 31;
    int gw = blockIdx.x * 8 + (tid >> 5);
    int nw = gridDim.x * 8;
    for (int e = gw; e < EE; e += nw) {
        int src = edge_index[e];
        int dst = edge_index[EE + e];
        int t = etype[e];
        float h0v = h_in[src * 64 + lane];
        float h1v = h_in[src * 64 + 32 + lane];
        const float2* Wt = (const float2*)(Wsh + t * 4096);
        float ax = 0.f, ay = 0.f;
#pragma unroll
        for (int k = 0; k < 64; k++) {
            float hk = __shfl_sync(0xffffffffu, (k < 32) ? h0v : h1v, k & 31);
            float2 w = Wt[k * 32 + lane];
            ax = fmaf(hk, w.x, ax);
            ay = fmaf(hk, w.y, ay);
        }
        float* p = h_out + dst * 64 + 2 * lane;
        asm volatile("red.global.add.v2.f32 [%0], {%1, %2};" :: "l"(p), "f"(ax), "f"(ay) : "memory");
    }
}

// ---------------- one Set2Set iteration: LSTM cell + attention pooling (block per graph) ----------------
__global__ void k_s2s(const float* __restrict__ h, const float* __restrict__ W_ih,
                      const float* __restrict__ W_hh, const float* __restrict__ b_ih,
                      const float* __restrict__ b_hh) {
    int b = blockIdx.x;
    int tid = threadIdx.x;
    int lane = tid & 31;
    int warp = tid >> 5;
    __shared__ float qs_s[128], hx_s[64], cx_s[64], gates_s[256], q_s[64], r_s[64];
    __shared__ float wred[8];
    __shared__ float m_sh, dinv_sh;

    if (tid < 128) qs_s[tid] = g_qstar[b * 128 + tid];
    if (tid < 64) { hx_s[tid] = g_hx[b * 64 + tid]; cx_s[tid] = g_cx[b * 64 + tid]; r_s[tid] = 0.f; }
    __syncthreads();

    // LSTM gates: each warp computes 32 gate dot products
    for (int g = 0; g < 32; g++) {
        int j = warp * 32 + g;
        float p = W_ih[j * 128 + lane]        * qs_s[lane]
                + W_ih[j * 128 + 32 + lane]   * qs_s[32 + lane]
                + W_ih[j * 128 + 64 + lane]   * qs_s[64 + lane]
                + W_ih[j * 128 + 96 + lane]   * qs_s[96 + lane]
                + W_hh[j * 64 + lane]         * hx_s[lane]
                + W_hh[j * 64 + 32 + lane]    * hx_s[32 + lane];
#pragma unroll
        for (int o = 16; o > 0; o >>= 1) p += __shfl_xor_sync(0xffffffffu, p, o);
        if (lane == 0) gates_s[j] = p + b_ih[j] + b_hh[j];
    }
    __syncthreads();
    if (tid < 64) {
        float ig = gates_s[tid], fg = gates_s[64 + tid], gg = gates_s[128 + tid], og = gates_s[192 + tid];
        float si = 1.f / (1.f + expf(-ig));
        float sf = 1.f / (1.f + expf(-fg));
        float so = 1.f / (1.f + expf(-og));
        float c = sf * cx_s[tid] + si * tanhf(gg);
        float hn = so * tanhf(c);
        g_cx[b * 64 + tid] = c;
        g_hx[b * 64 + tid] = hn;
        q_s[tid] = hn;
    }
    __syncthreads();

    int start = g_off[b], end = g_off[b + 1];
    const float2* h2 = (const float2*)h;

    // pass 1: e[n] = h[n] . q  and segment max
    float mloc = -INFINITY;
    for (int n = start + warp; n < end; n += 8) {
        float2 hv = h2[n * 32 + lane];
        float p = hv.x * q_s[2 * lane] + hv.y * q_s[2 * lane + 1];
#pragma unroll
        for (int o = 16; o > 0; o >>= 1) p += __shfl_xor_sync(0xffffffffu, p, o);
        if (lane == 0) g_e[n] = p;
        mloc = fmaxf(mloc, p);
    }
    if (lane == 0) wred[warp] = mloc;
    __syncthreads();
    if (tid == 0) {
        float m = wred[0];
        for (int i = 1; i < 8; i++) m = fmaxf(m, wred[i]);
        m_sh = m;
    }
    __syncthreads();
    float m = m_sh;

    // pass 2: a = exp(e - m), segment sum
    float sloc = 0.f;
    for (int n = start + tid; n < end; n += 256) {
        float a = expf(g_e[n] - m);
        g_e[n] = a;
        sloc += a;
    }
#pragma unroll
    for (int o = 16; o > 0; o >>= 1) sloc += __shfl_xor_sync(0xffffffffu, sloc, o);
    if (lane == 0) wred[warp] = sloc;
    __syncthreads();
    if (tid == 0) {
        float d = 0.f;
        for (int i = 0; i < 8; i++) d += wred[i];
        dinv_sh = (d == 0.f) ? 1.f : 1.f / d;
    }
    __syncthreads();
    float dinv = dinv_sh;

    // pass 3: r = sum a*h / denom
    float rx = 0.f, ry = 0.f;
    for (int n = start + warp; n < end; n += 8) {
        float a = g_e[n];
        float2 hv = h2[n * 32 + lane];
        rx = fmaf(a, hv.x, rx);
        ry = fmaf(a, hv.y, ry);
    }
    atomicAdd(&r_s[2 * lane], rx * dinv);
    atomicAdd(&r_s[2 * lane + 1], ry * dinv);
    __syncthreads();
    if (tid < 64) g_qstar[b * 128 + tid] = q_s[tid];
    else if (tid < 128) g_qstar[b * 128 + tid] = r_s[tid - 64];
}

// ---------------- output MLP: relu(q_star @ W_o1 + b_o1) @ W_o2 + b_o2 ----------------
__global__ void k_out(const float* __restrict__ W_o1, const float* __restrict__ b_o1,
                      const float* __restrict__ W_o2, const float* __restrict__ b_o2,
                      float* __restrict__ out) {
    int b = blockIdx.x, j = threadIdx.x;   // 64 threads
    __shared__ float red[64];
    float acc = b_o1[j];
#pragma unroll 8
    for (int k = 0; k < 128; k++)
        acc = fmaf(g_qstar[b * 128 + k], W_o1[k * 64 + j], acc);
    acc = fmaxf(acc, 0.f);
    red[j] = acc * W_o2[j];
    __syncthreads();
    for (int s = 32; s > 0; s >>= 1) {
        if (j < s) red[j] += red[j + s];
        __syncthreads();
    }
    if (j == 0) out[b] = red[0] + b_o2[0];
}

// ---------------- launch ----------------
extern "C" void kernel_launch(void* const* d_in, const int* in_sizes, int n_in,
                              void* d_out, int out_size) {
    const float* node_feat = (const float*)d_in[0];
    const int*   node_type = (const int*)d_in[1];
    const int*   edge_index = (const int*)d_in[2];
    const int*   edge_type = (const int*)d_in[3];
    const int*   batch = (const int*)d_in[4];
    const float* W_emb = (const float*)d_in[5];
    const float* b_emb = (const float*)d_in[6];
    const float* W_e1 = (const float*)d_in[7];
    const float* b_e1 = (const float*)d_in[8];
    const float* W_e2 = (const float*)d_in[9];
    const float* b_e2 = (const float*)d_in[10];
    const float* roots = (const float*)d_in[11];
    const float* conv_bias = (const float*)d_in[12];
    const float* W_ih = (const float*)d_in[13];
    const float* W_hh = (const float*)d_in[14];
    const float* b_ih = (const float*)d_in[15];
    const float* b_hh = (const float*)d_in[16];
    const float* W_o1 = (const float*)d_in[17];
    const float* b_o1 = (const float*)d_in[18];
    const float* W_o2 = (const float*)d_in[19];
    const float* b_o2 = (const float*)d_in[20];
    float* out = (float*)d_out;

    float *h0, *h1;
    cudaGetSymbolAddress((void**)&h0, g_h0);
    cudaGetSymbolAddress((void**)&h1, g_h1);

    cudaFuncSetAttribute(k_edge, cudaFuncAttributeMaxDynamicSharedMemorySize, 5 * 4096 * 4);

    k_edgemats<<<dim3(16, 5), 256>>>(W_e1, b_e1, W_e2, b_e2);
    k_embed<<<(NN * HH) / 256, 256>>>(node_feat, node_type, W_emb, b_emb, h0);
    k_init<<<64, 256>>>(batch);

    float* hin = h0;
    float* hout = h1;
    for (int i = 0; i < MPI; i++) {
        k_root<<<NN / 8, 256>>>(hin, roots + i * HH * HH, conv_bias + i * HH, hout);
        k_edge<<<296, 256, 5 * 4096 * 4>>>(hin, edge_index, edge_type, hout);
        float* t = hin; hin = hout; hout = t;
    }
    for (int it = 0; it < S2SI; it++)
        k_s2s<<<BB, 256>>>(hin, W_ih, W_hh, b_ih, b_hh);
    k_out<<<BB, 64>>>(W_o1, b_o1, W_o2, b_o2, out);
}

// round 4
// speedup vs baseline: 1.1963x; 1.1963x over previous
#include <cuda_runtime.h>
#include <math.h>

#define NN 20000
#define EE 50000
#define BB 128
#define HH 64
#define FEATD 28
#define NTYPES 100
#define MPI 3
#define S2SI 4
#define HCAP 768     // max cached nodes per graph in s2s

// ---------------- scratch ----------------
__device__ __align__(16) float g_Wq[5 * 64 * 32 * 4];    // edge weights, dup-pair layout
__device__ __align__(16) float g_RWq[MPI * 64 * 32 * 4]; // root weights, dup-pair layout
__device__ __align__(16) float g_h0[NN * HH];
__device__ __align__(16) float g_h1[NN * HH];
__device__ float g_e[NN];          // s2s fallback buffer
__device__ int   g_esrc[EE];
__device__ int   g_edst[EE];
__device__ int   g_cnt[5];
__device__ int   g_toff[6];
__device__ int   g_cur[5];

__device__ __forceinline__ void ffma2(unsigned long long& d, unsigned long long a, unsigned long long b) {
    asm("fma.rn.f32x2 %0, %1, %2, %0;" : "+l"(d) : "l"(a), "l"(b));
}
__device__ __forceinline__ float f2lo(unsigned long long v) { return __uint_as_float((unsigned)v); }
__device__ __forceinline__ float f2hi(unsigned long long v) { return __uint_as_float((unsigned)(v >> 32)); }

// ---------------- edge matrices: W_t = relu(W_e1[t]+b_e1) @ W_e2 + b_e2, dup layout ----------------
__global__ void k_edgemats(const float* __restrict__ We1, const float* __restrict__ be1,
                           const float* __restrict__ We2, const float* __restrict__ be2) {
    int t = blockIdx.y;
    int j = blockIdx.x * 256 + threadIdx.x;   // 0..4095 = hin*64+hout
    if (t == 0 && blockIdx.x == 0 && threadIdx.x < 5) g_cnt[threadIdx.x] = 0;
    __shared__ float relu_s[64];
    if (threadIdx.x < 64) {
        float v = We1[t * 64 + threadIdx.x] + be1[threadIdx.x];
        relu_s[threadIdx.x] = v > 0.f ? v : 0.f;
    }
    __syncthreads();
    float acc = be2[j];
#pragma unroll 8
    for (int m = 0; m < 64; m++)
        acc = fmaf(relu_s[m], We2[m * 4096 + j], acc);
    int hin = j >> 6, hout = j & 63;
    float* q = g_Wq + (((t * 64 + hin) * 32 + (hout & 31)) << 2) + ((hout >> 5) << 1);
    q[0] = acc; q[1] = acc;
}

// ---------------- root weights -> dup layout ----------------
__global__ void k_rootq(const float* __restrict__ roots) {
    int idx = blockIdx.x * 256 + threadIdx.x;   // 0..3*4096-1
    int layer = idx >> 12, j = idx & 4095;
    int hin = j >> 6, hout = j & 63;
    float v = roots[idx];
    float* q = g_RWq + (((layer * 64 + hin) * 32 + (hout & 31)) << 2) + ((hout >> 5) << 1);
    q[0] = v; q[1] = v;
}

// ---------------- node embedding ----------------
__global__ void k_embed(const float* __restrict__ feat, const int* __restrict__ ntype,
                        const float* __restrict__ W_emb, const float* __restrict__ b_emb,
                        float* __restrict__ h) {
    int idx = blockIdx.x * 256 + threadIdx.x;
    int n = idx >> 6, o = idx & 63;
    int t = ntype[n];
    float acc = W_emb[t * 64 + o] + b_emb[o];
#pragma unroll
    for (int f = 0; f < FEATD; f++)
        acc = fmaf(feat[n * FEATD + f], W_emb[(NTYPES + f) * 64 + o], acc);
    h[idx] = acc;
}

// ---------------- edge-type histogram ----------------
__global__ void k_hist(const int* __restrict__ etype) {
    __shared__ int c_s[5];
    int tid = threadIdx.x;
    if (tid < 5) c_s[tid] = 0;
    __syncthreads();
    int e = blockIdx.x * 256 + tid;
    if (e < EE) atomicAdd(&c_s[etype[e]], 1);
    __syncthreads();
    if (tid < 5 && c_s[tid]) atomicAdd(&g_cnt[tid], c_s[tid]);
}

// ---------------- prefix scan (tiny) + cursor init ----------------
__global__ void k_scan() {
    if (threadIdx.x == 0) {
        int s = 0;
        for (int t = 0; t < 5; t++) { g_toff[t] = s; g_cur[t] = s; s += g_cnt[t]; }
        g_toff[5] = s;
    }
}

// ---------------- scatter edges into type buckets ----------------
__global__ void k_scatter(const int* __restrict__ edge_index, const int* __restrict__ etype) {
    int e = blockIdx.x * 256 + threadIdx.x;
    int lane = threadIdx.x & 31;
    bool v = e < EE;
    int t = v ? etype[e] : -1;
#pragma unroll
    for (int tt = 0; tt < 5; tt++) {
        unsigned mask = __ballot_sync(0xffffffffu, t == tt);
        if (!mask) continue;
        int leader = __ffs(mask) - 1;
        int base = 0;
        if (lane == leader) base = atomicAdd(&g_cur[tt], __popc(mask));
        base = __shfl_sync(0xffffffffu, base, leader);
        if (t == tt) {
            int pos = base + __popc(mask & ((1u << lane) - 1u));
            g_esrc[pos] = edge_index[e];
            g_edst[pos] = edge_index[EE + e];
        }
    }
}

// ---------------- root GEMM: h_out = h_in @ root + bias (f32x2, 8 nodes/warp) ----------------
__global__ void __launch_bounds__(256) k_rootmm(const float* __restrict__ h_in, int layer,
                                                const float* __restrict__ bias,
                                                float* __restrict__ h_out) {
    extern __shared__ float sm[];
    float* Wq = sm;                              // 8192 floats
    int tid = threadIdx.x, lane = tid & 31, warp = tid >> 5;
    float* hst = sm + 8192 + warp * 640;
    const float4* gq = (const float4*)(g_RWq + layer * 8192);
    float4* sq = (float4*)Wq;
    for (int i = tid; i < 64 * 32; i += 256) sq[i] = gq[i];
    __syncthreads();
    const ulonglong2* W2 = (const ulonglong2*)Wq;
    const unsigned long long* h64 = (const unsigned long long*)hst;
    float blo = bias[lane], bhi = bias[32 + lane];

    int tile = blockIdx.x * 8 + warp;
    if (tile >= NN / 8) return;
    int n0 = tile * 8;
    float hA[8], hB[8];
#pragma unroll
    for (int e = 0; e < 8; e++) {
        hA[e] = h_in[(n0 + e) * 64 + lane];
        hB[e] = h_in[(n0 + e) * 64 + 32 + lane];
    }
#pragma unroll
    for (int e = 0; e < 8; e++) { hst[lane * 10 + e] = hA[e]; hst[(32 + lane) * 10 + e] = hB[e]; }
    __syncwarp();
    unsigned long long aL[4] = {0,0,0,0}, aH[4] = {0,0,0,0};
#pragma unroll 8
    for (int k = 0; k < 64; k++) {
        ulonglong2 w = W2[k * 32 + lane];
#pragma unroll
        for (int p = 0; p < 4; p++) {
            unsigned long long hp = h64[k * 5 + p];
            ffma2(aL[p], hp, w.x);
            ffma2(aH[p], hp, w.y);
        }
    }
#pragma unroll
    for (int p = 0; p < 4; p++) {
        int n = n0 + 2 * p;
        h_out[n * 64 + lane]            = f2lo(aL[p]) + blo;
        h_out[n * 64 + 32 + lane]       = f2lo(aH[p]) + bhi;
        h_out[(n + 1) * 64 + lane]      = f2hi(aL[p]) + blo;
        h_out[(n + 1) * 64 + 32 + lane] = f2hi(aH[p]) + bhi;
    }
}

// ---------------- edge scatter: h_out[dst] += h_in[src] @ W_{type} (bucketed, f32x2) ----------------
__global__ void __launch_bounds__(256) k_edge(const float* __restrict__ h_in,
                                              float* __restrict__ h_out) {
    extern __shared__ float sm[];
    float* Wq = sm;                              // 8192 floats (this type only)
    int t = blockIdx.y;
    int tid = threadIdx.x, lane = tid & 31, warp = tid >> 5;
    float* hst = sm + 8192 + warp * 640;
    const float4* gq = (const float4*)(g_Wq + t * 8192);
    float4* sq = (float4*)Wq;
    for (int i = tid; i < 64 * 32; i += 256) sq[i] = gq[i];
    __syncthreads();
    const ulonglong2* W2 = (const ulonglong2*)Wq;
    const unsigned long long* h64 = (const unsigned long long*)hst;
    int lo = g_toff[t], hi = g_toff[t + 1];

    for (int base = lo + (blockIdx.x * 8 + warp) * 8; base < hi; base += gridDim.x * 64) {
        int m = hi - base; if (m > 8) m = 8;
        int srcs[8], dsts[8];
        float hA[8], hB[8];
#pragma unroll
        for (int e = 0; e < 8; e++) {
            bool v = e < m;
            srcs[e] = v ? g_esrc[base + e] : 0;
            dsts[e] = v ? g_edst[base + e] : 0;
        }
#pragma unroll
        for (int e = 0; e < 8; e++) {
            hA[e] = (e < m) ? h_in[srcs[e] * 64 + lane] : 0.f;
            hB[e] = (e < m) ? h_in[srcs[e] * 64 + 32 + lane] : 0.f;
        }
        __syncwarp();
#pragma unroll
        for (int e = 0; e < 8; e++) { hst[lane * 10 + e] = hA[e]; hst[(32 + lane) * 10 + e] = hB[e]; }
        __syncwarp();
        unsigned long long aL[4] = {0,0,0,0}, aH[4] = {0,0,0,0};
#pragma unroll 8
        for (int k = 0; k < 64; k++) {
            ulonglong2 w = W2[k * 32 + lane];
#pragma unroll
            for (int p = 0; p < 4; p++) {
                unsigned long long hp = h64[k * 5 + p];
                ffma2(aL[p], hp, w.x);
                ffma2(aH[p], hp, w.y);
            }
        }
#pragma unroll
        for (int p = 0; p < 4; p++) {
            if (2 * p < m) {
                float* pt = h_out + dsts[2 * p] * 64;
                asm volatile("red.global.add.f32 [%0], %1;" :: "l"(pt + lane), "f"(f2lo(aL[p])) : "memory");
                asm volatile("red.global.add.f32 [%0], %1;" :: "l"(pt + 32 + lane), "f"(f2lo(aH[p])) : "memory");
            }
            if (2 * p + 1 < m) {
                float* pt = h_out + dsts[2 * p + 1] * 64;
                asm volatile("red.global.add.f32 [%0], %1;" :: "l"(pt + lane), "f"(f2hi(aL[p])) : "memory");
                asm volatile("red.global.add.f32 [%0], %1;" :: "l"(pt + 32 + lane), "f"(f2hi(aH[p])) : "memory");
            }
        }
        __syncwarp();
    }
}

// ---------------- fused Set2Set (all 4 iterations) + output MLP ----------------
__global__ void __launch_bounds__(256) k_s2s_all(
        const float* __restrict__ h, const int* __restrict__ batch,
        const float* __restrict__ W_ih, const float* __restrict__ W_hh,
        const float* __restrict__ b_ih, const float* __restrict__ b_hh,
        const float* __restrict__ W_o1, const float* __restrict__ b_o1,
        const float* __restrict__ W_o2, const float* __restrict__ b_o2,
        float* __restrict__ out) {
    extern __shared__ float hc[];   // HCAP*64 floats
    __shared__ float qs_s[128], hx_s[64], cx_s[64], gates_s[256], q_s[64], r_s[64];
    __shared__ float wred[8], m_sh, dinv_sh, red_s[64];
    __shared__ float e_s[HCAP];
    __shared__ int s_off[2];
    int b = blockIdx.x, tid = threadIdx.x, lane = tid & 31, warp = tid >> 5;

    if (tid < 2) {
        int tgt = b + tid, lo = 0, hi = NN;
        while (lo < hi) { int mid = (lo + hi) >> 1; if (batch[mid] < tgt) lo = mid + 1; else hi = mid; }
        s_off[tid] = lo;
    }
    if (tid < 128) qs_s[tid] = 0.f;
    if (tid < 64) { hx_s[tid] = 0.f; cx_s[tid] = 0.f; }
    __syncthreads();
    int start = s_off[0], end = s_off[1], cnt = end - start;
    bool cached = (cnt <= HCAP);
    if (cached) for (int i = tid; i < cnt * 64; i += 256) hc[i] = h[start * 64 + i];
    __syncthreads();
    const float2* h2g = (const float2*)h;
    const float2* h2c = (const float2*)hc;

    for (int it = 0; it < S2SI; it++) {
        // LSTM gates: each warp computes 32 gate dot products (coalesced rows)
        for (int g = 0; g < 32; g++) {
            int j = warp * 32 + g;
            float p = W_ih[j * 128 + lane]      * qs_s[lane]
                    + W_ih[j * 128 + 32 + lane] * qs_s[32 + lane]
                    + W_ih[j * 128 + 64 + lane] * qs_s[64 + lane]
                    + W_ih[j * 128 + 96 + lane] * qs_s[96 + lane]
                    + W_hh[j * 64 + lane]       * hx_s[lane]
                    + W_hh[j * 64 + 32 + lane]  * hx_s[32 + lane];
#pragma unroll
            for (int o = 16; o > 0; o >>= 1) p += __shfl_xor_sync(0xffffffffu, p, o);
            if (lane == 0) gates_s[j] = p + b_ih[j] + b_hh[j];
        }
        __syncthreads();
        if (tid < 64) {
            float ig = gates_s[tid], fg = gates_s[64 + tid], gg = gates_s[128 + tid], og = gates_s[192 + tid];
            float si = 1.f / (1.f + expf(-ig));
            float sf = 1.f / (1.f + expf(-fg));
            float so = 1.f / (1.f + expf(-og));
            float c = sf * cx_s[tid] + si * tanhf(gg);
            float hn = so * tanhf(c);
            cx_s[tid] = c; hx_s[tid] = hn; q_s[tid] = hn;
        } else if (tid < 128) {
            r_s[tid - 64] = 0.f;
        }
        __syncthreads();
        float qx = q_s[2 * lane], qy = q_s[2 * lane + 1];

        // pass 1: e = h.q, segment max
        float mloc = -INFINITY;
        for (int i = warp; i < cnt; i += 8) {
            float2 hv = cached ? h2c[i * 32 + lane] : h2g[(start + i) * 32 + lane];
            float p = hv.x * qx + hv.y * qy;
#pragma unroll
            for (int o = 16; o > 0; o >>= 1) p += __shfl_xor_sync(0xffffffffu, p, o);
            if (lane == 0) { if (cached) e_s[i] = p; else g_e[start + i] = p; }
            mloc = fmaxf(mloc, p);
        }
        if (lane == 0) wred[warp] = mloc;
        __syncthreads();
        if (tid == 0) {
            float m = wred[0];
            for (int i = 1; i < 8; i++) m = fmaxf(m, wred[i]);
            m_sh = m;
        }
        __syncthreads();
        float m = m_sh;

        // pass 2: a = exp(e-m), segment sum
        float sloc = 0.f;
        for (int i = tid; i < cnt; i += 256) {
            float a = expf((cached ? e_s[i] : g_e[start + i]) - m);
            if (cached) e_s[i] = a; else g_e[start + i] = a;
            sloc += a;
        }
#pragma unroll
        for (int o = 16; o > 0; o >>= 1) sloc += __shfl_xor_sync(0xffffffffu, sloc, o);
        if (lane == 0) wred[warp] = sloc;
        __syncthreads();
        if (tid == 0) {
            float d = 0.f;
            for (int i = 0; i < 8; i++) d += wred[i];
            dinv_sh = (d == 0.f) ? 1.f : 1.f / d;
        }
        __syncthreads();
        float dinv = dinv_sh;

        // pass 3: r = sum a*h * dinv
        float rx = 0.f, ry = 0.f;
        for (int i = warp; i < cnt; i += 8) {
            float a = cached ? e_s[i] : g_e[start + i];
            float2 hv = cached ? h2c[i * 32 + lane] : h2g[(start + i) * 32 + lane];
            rx = fmaf(a, hv.x, rx);
            ry = fmaf(a, hv.y, ry);
        }
        atomicAdd(&r_s[2 * lane], rx * dinv);
        atomicAdd(&r_s[2 * lane + 1], ry * dinv);
        __syncthreads();
        if (tid < 64) qs_s[tid] = q_s[tid];
        else if (tid < 128) qs_s[tid] = r_s[tid - 64];
        __syncthreads();
    }

    // output MLP: relu(q_star @ W_o1 + b_o1) @ W_o2 + b_o2
    if (tid < 64) {
        float acc = b_o1[tid];
#pragma unroll 8
        for (int k = 0; k < 128; k++)
            acc = fmaf(qs_s[k], W_o1[k * 64 + tid], acc);
        acc = fmaxf(acc, 0.f);
        red_s[tid] = acc * W_o2[tid];
    }
    __syncthreads();
    if (tid < 32) {
        float v = red_s[tid] + red_s[tid + 32];
#pragma unroll
        for (int o = 16; o > 0; o >>= 1) v += __shfl_xor_sync(0xffffffffu, v, o);
        if (tid == 0) out[b] = v + b_o2[0];
    }
}

// ---------------- launch ----------------
extern "C" void kernel_launch(void* const* d_in, const int* in_sizes, int n_in,
                              void* d_out, int out_size) {
    const float* node_feat = (const float*)d_in[0];
    const int*   node_type = (const int*)d_in[1];
    const int*   edge_index = (const int*)d_in[2];
    const int*   edge_type = (const int*)d_in[3];
    const int*   batch = (const int*)d_in[4];
    const float* W_emb = (const float*)d_in[5];
    const float* b_emb = (const float*)d_in[6];
    const float* W_e1 = (const float*)d_in[7];
    const float* b_e1 = (const float*)d_in[8];
    const float* W_e2 = (const float*)d_in[9];
    const float* b_e2 = (const float*)d_in[10];
    const float* roots = (const float*)d_in[11];
    const float* conv_bias = (const float*)d_in[12];
    const float* W_ih = (const float*)d_in[13];
    const float* W_hh = (const float*)d_in[14];
    const float* b_ih = (const float*)d_in[15];
    const float* b_hh = (const float*)d_in[16];
    const float* W_o1 = (const float*)d_in[17];
    const float* b_o1 = (const float*)d_in[18];
    const float* W_o2 = (const float*)d_in[19];
    const float* b_o2 = (const float*)d_in[20];
    float* out = (float*)d_out;

    float *h0, *h1;
    cudaGetSymbolAddress((void**)&h0, g_h0);
    cudaGetSymbolAddress((void**)&h1, g_h1);

    const int MM_SMEM = (8192 + 8 * 640) * 4;   // 53248
    cudaFuncSetAttribute(k_edge, cudaFuncAttributeMaxDynamicSharedMemorySize, MM_SMEM);
    cudaFuncSetAttribute(k_rootmm, cudaFuncAttributeMaxDynamicSharedMemorySize, MM_SMEM);
    cudaFuncSetAttribute(k_s2s_all, cudaFuncAttributeMaxDynamicSharedMemorySize, HCAP * 64 * 4);

    k_edgemats<<<dim3(16, 5), 256>>>(W_e1, b_e1, W_e2, b_e2);
    k_rootq<<<48, 256>>>(roots);
    k_embed<<<(NN * HH) / 256, 256>>>(node_feat, node_type, W_emb, b_emb, h0);
    k_hist<<<(EE + 255) / 256, 256>>>(edge_type);
    k_scan<<<1, 32>>>();
    k_scatter<<<(EE + 255) / 256, 256>>>(edge_index, edge_type);

    float* hin = h0;
    float* hout = h1;
    for (int i = 0; i < MPI; i++) {
        k_rootmm<<<(NN / 8 + 7) / 8, 256, MM_SMEM>>>(hin, i, conv_bias + i * HH, hout);
        k_edge<<<dim3(36, 5), 256, MM_SMEM>>>(hin, hout);
        float* t = hin; hin = hout; hout = t;
    }
    k_s2s_all<<<BB, 256, HCAP * 64 * 4>>>(hin, batch, W_ih, W_hh, b_ih, b_hh,
                                          W_o1, b_o1, W_o2, b_o2, out);
}

// round 5
// speedup vs baseline: 1.5099x; 1.2622x over previous
#include <cuda_runtime.h>
#include <math.h>

#define NN 20000
#define EE 50000
#define BB 128
#define HH 64
#define FEATD 28
#define NTYPES 100
#define MPI 3
#define S2SI 4
#define HCAP 768

#define PB_EM   80      // edge-matrix blocks
#define PB_EMB  5000    // embedding blocks
#define PB_HIST 196     // histogram-partial blocks
#define PB_ZERO 3750    // zeroing blocks (3 * NN*64 floats / (256*4))
#define NB_ROOT 157     // root blocks in fused MP kernel (1250 groups of 16 nodes / 8 warps)
#define NB_EDGE 180     // edge blocks (36 chunks x 5 types)

// ---------------- scratch ----------------
__device__ __align__(16) float g_W5[5 * 64 * 64];        // edge matrices, natural [t][hin][hout]
__device__ __align__(16) float g_h0[NN * HH];            // root buffers (ping-pong)
__device__ __align__(16) float g_h1[NN * HH];
__device__ __align__(16) float g_a[3 * NN * HH];         // edge accumulators A1,A2,A3 (pre-zeroed)
__device__ float g_e[NN];
__device__ int   g_part[PB_HIST * 5];
__device__ int   g_toff[6];
__device__ int   g_esrc[EE];
__device__ int   g_edst[EE];

__device__ __forceinline__ void ffma2(unsigned long long& d, unsigned long long a, unsigned long long b) {
    asm("fma.rn.f32x2 %0, %1, %2, %0;" : "+l"(d) : "l"(a), "l"(b));
}
__device__ __forceinline__ float f2lo(unsigned long long v) { return __uint_as_float((unsigned)v); }
__device__ __forceinline__ float f2hi(unsigned long long v) { return __uint_as_float((unsigned)(v >> 32)); }

// ================= L1: mega prep (edgemats | embed | hist partials | zero acc) =================
__global__ void __launch_bounds__(256) k_prep(
        const float* __restrict__ feat, const int* __restrict__ ntype,
        const float* __restrict__ W_emb, const float* __restrict__ b_emb,
        const float* __restrict__ We1, const float* __restrict__ be1,
        const float* __restrict__ We2, const float* __restrict__ be2,
        const int* __restrict__ etype) {
    int b = blockIdx.x, tid = threadIdx.x;
    if (b < PB_EM) {
        // W_t = relu(W_e1[t]+b_e1) @ W_e2 + b_e2, natural layout
        int t = b >> 4;
        int jj = (b & 15) * 256 + tid;   // hin*64+hout
        __shared__ float relu_s[64];
        if (tid < 64) {
            float v = We1[t * 64 + tid] + be1[tid];
            relu_s[tid] = v > 0.f ? v : 0.f;
        }
        __syncthreads();
        float acc = be2[jj];
#pragma unroll 8
        for (int m = 0; m < 64; m++)
            acc = fmaf(relu_s[m], We2[m * 4096 + jj], acc);
        g_W5[t * 4096 + jj] = acc;
    } else if (b < PB_EM + PB_EMB) {
        // node embedding -> g_h0
        int idx = (b - PB_EM) * 256 + tid;
        int n = idx >> 6, o = idx & 63;
        int t = ntype[n];
        float acc = W_emb[t * 64 + o] + b_emb[o];
#pragma unroll
        for (int f = 0; f < FEATD; f++)
            acc = fmaf(feat[n * FEATD + f], W_emb[(NTYPES + f) * 64 + o], acc);
        g_h0[idx] = acc;
    } else if (b < PB_EM + PB_EMB + PB_HIST) {
        // per-block edge-type counts (plain stores, no init needed)
        int hb = b - (PB_EM + PB_EMB);
        __shared__ int c_s[5];
        if (tid < 5) c_s[tid] = 0;
        __syncthreads();
        int e = hb * 256 + tid;
        if (e < EE) atomicAdd(&c_s[etype[e]], 1);
        __syncthreads();
        if (tid < 5) g_part[hb * 5 + tid] = c_s[tid];
    } else {
        // zero the 3 accumulator buffers
        int zb = b - (PB_EM + PB_EMB + PB_HIST);
        ((float4*)g_a)[zb * 256 + tid] = make_float4(0.f, 0.f, 0.f, 0.f);
    }
}

// ================= L2: deterministic bucket scatter (rank = global prefix of partials) =================
__global__ void __launch_bounds__(256) k_scat(const int* __restrict__ edge_index,
                                              const int* __restrict__ etype) {
    __shared__ int cnt_s[5], prior_s[5], base_s[5];
    __shared__ int wcnt[8][5];
    int b = blockIdx.x, tid = threadIdx.x, lane = tid & 31, warp = tid >> 5;
    if (tid < 5) {
        int tot = 0, prior = 0;
        for (int b2 = 0; b2 < PB_HIST; b2++) {
            int c = g_part[b2 * 5 + tid];
            tot += c;
            if (b2 < b) prior += c;
        }
        cnt_s[tid] = tot; prior_s[tid] = prior;
    }
    __syncthreads();
    if (tid == 0) {
        int s = 0;
        for (int t = 0; t < 5; t++) {
            base_s[t] = s + prior_s[t];
            if (b == 0) g_toff[t] = s;
            s += cnt_s[t];
        }
        if (b == 0) g_toff[5] = s;
    }
    __syncthreads();
    int e = b * 256 + tid;
    int t = (e < EE) ? etype[e] : -1;
#pragma unroll
    for (int tt = 0; tt < 5; tt++) {
        unsigned mk = __ballot_sync(0xffffffffu, t == tt);
        if (lane == 0) wcnt[warp][tt] = __popc(mk);
    }
    __syncthreads();
#pragma unroll
    for (int tt = 0; tt < 5; tt++) {
        unsigned mk = __ballot_sync(0xffffffffu, t == tt);
        if (!mk) continue;
        int pre = 0;
        for (int w2 = 0; w2 < warp; w2++) pre += wcnt[w2][tt];
        if (t == tt) {
            int pos = base_s[tt] + pre + __popc(mk & ((1u << lane) - 1u));
            g_esrc[pos] = edge_index[e];
            g_edst[pos] = edge_index[EE + e];
        }
    }
}

// ================= fused MP iteration: root GEMM blocks + edge-scatter blocks =================
// 16-work-unit groups: lanes 0-15 own outputs [4j,4j+4) of units 0..7, lanes 16-31 of units 8..15.
__device__ __forceinline__ void mm16(const float* __restrict__ Wsm, const float2* __restrict__ stgh,
                                     int j, unsigned long long acc[8][2]) {
#pragma unroll 4
    for (int k = 0; k < 64; k++) {
        ulonglong2 w = *(const ulonglong2*)(Wsm + k * 64 + 4 * j);
#pragma unroll
        for (int e = 0; e < 8; e++) {
            unsigned long long hd = *(const unsigned long long*)(stgh + e * 64 + k);
            ffma2(acc[e][0], hd, w.x);
            ffma2(acc[e][1], hd, w.y);
        }
    }
}

__global__ void __launch_bounds__(256) k_mp(const float* __restrict__ hinR,
                                            const float* __restrict__ hinA,
                                            float* __restrict__ houtR,
                                            float* __restrict__ houtA,
                                            const float* __restrict__ rootW,
                                            const float* __restrict__ bias,
                                            int has_acc) {
    extern __shared__ float sm[];
    float* Wsm = sm;                                    // 4096 floats
    int tid = threadIdx.x, lane = tid & 31, warp = tid >> 5;
    int j = lane & 15, half = lane >> 4;
    float2* stg = (float2*)(sm + 4096) + warp * 1024;   // 16 units x 64 k (dup float2)
    float2* stgh = stg + half * 512;
    bool isRoot = blockIdx.x < NB_ROOT;
    int idx_e = blockIdx.x - NB_ROOT;
    int t = isRoot ? 0 : (idx_e % 5);

    const float4* wsrc = (const float4*)(isRoot ? rootW : (g_W5 + t * 4096));
    float4* wdst = (float4*)Wsm;
#pragma unroll
    for (int i = 0; i < 4; i++) wdst[i * 256 + tid] = wsrc[i * 256 + tid];
    __syncthreads();

    const float2* hR2 = (const float2*)hinR;
    const float2* hA2 = (const float2*)hinA;

    if (isRoot) {
        int g = blockIdx.x * 8 + warp;
        if (g >= NN / 16) return;
        int n0 = g * 16;
#pragma unroll
        for (int E = 0; E < 16; E++) {
            float2 hv = hR2[(n0 + E) * 32 + lane];
            if (has_acc) { float2 av = hA2[(n0 + E) * 32 + lane]; hv.x += av.x; hv.y += av.y; }
            stg[E * 64 + 2 * lane]     = make_float2(hv.x, hv.x);
            stg[E * 64 + 2 * lane + 1] = make_float2(hv.y, hv.y);
        }
        __syncwarp();
        unsigned long long acc[8][2];
#pragma unroll
        for (int e = 0; e < 8; e++) { acc[e][0] = 0ull; acc[e][1] = 0ull; }
        mm16(Wsm, stgh, j, acc);
        float4 b4 = ((const float4*)bias)[j];
#pragma unroll
        for (int e = 0; e < 8; e++) {
            int n = n0 + e + half * 8;
            float4 o = make_float4(f2lo(acc[e][0]) + b4.x, f2hi(acc[e][0]) + b4.y,
                                   f2lo(acc[e][1]) + b4.z, f2hi(acc[e][1]) + b4.w);
            ((float4*)houtR)[n * 16 + j] = o;
        }
    } else {
        int chunk = idx_e / 5;
        int lo = g_toff[t], hi = g_toff[t + 1];
        for (int base = lo + (chunk * 8 + warp) * 16; base < hi; base += 36 * 8 * 16) {
            int m = hi - base; if (m > 16) m = 16;
#pragma unroll
            for (int E = 0; E < 16; E++) {
                float2 hv = make_float2(0.f, 0.f);
                if (E < m) {
                    int s = g_esrc[base + E];
                    hv = hR2[s * 32 + lane];
                    if (has_acc) { float2 av = hA2[s * 32 + lane]; hv.x += av.x; hv.y += av.y; }
                }
                stg[E * 64 + 2 * lane]     = make_float2(hv.x, hv.x);
                stg[E * 64 + 2 * lane + 1] = make_float2(hv.y, hv.y);
            }
            __syncwarp();
            unsigned long long acc[8][2];
#pragma unroll
            for (int e = 0; e < 8; e++) { acc[e][0] = 0ull; acc[e][1] = 0ull; }
            mm16(Wsm, stgh, j, acc);
#pragma unroll
            for (int e = 0; e < 8; e++) {
                int E = e + half * 8;
                if (E < m) {
                    int d = g_edst[base + E];
                    float* p = houtA + d * 64 + 4 * j;
                    asm volatile("red.global.add.v2.f32 [%0], {%1, %2};"
                                 :: "l"(p), "f"(f2lo(acc[e][0])), "f"(f2hi(acc[e][0])) : "memory");
                    asm volatile("red.global.add.v2.f32 [%0], {%1, %2};"
                                 :: "l"(p + 2), "f"(f2lo(acc[e][1])), "f"(f2hi(acc[e][1])) : "memory");
                }
            }
            __syncwarp();
        }
    }
}

// ================= fused Set2Set (4 iterations) + output MLP; h = hR + hA =================
__global__ void __launch_bounds__(256) k_s2s_all(
        const float* __restrict__ hR, const float* __restrict__ hA,
        const int* __restrict__ batch,
        const float* __restrict__ W_ih, const float* __restrict__ W_hh,
        const float* __restrict__ b_ih, const float* __restrict__ b_hh,
        const float* __restrict__ W_o1, const float* __restrict__ b_o1,
        const float* __restrict__ W_o2, const float* __restrict__ b_o2,
        float* __restrict__ out) {
    extern __shared__ float hc[];
    __shared__ float qs_s[128], hx_s[64], cx_s[64], gates_s[256], q_s[64], r_s[64];
    __shared__ float wred[8], m_sh, dinv_sh, red_s[64];
    __shared__ float e_s[HCAP];
    __shared__ int s_off[2];
    int b = blockIdx.x, tid = threadIdx.x, lane = tid & 31, warp = tid >> 5;

    if (tid < 2) {
        int tgt = b + tid, lo = 0, hi = NN;
        while (lo < hi) { int mid = (lo + hi) >> 1; if (batch[mid] < tgt) lo = mid + 1; else hi = mid; }
        s_off[tid] = lo;
    }
    if (tid < 128) qs_s[tid] = 0.f;
    if (tid < 64) { hx_s[tid] = 0.f; cx_s[tid] = 0.f; }
    __syncthreads();
    int start = s_off[0], end = s_off[1], cnt = end - start;
    bool cached = (cnt <= HCAP);
    if (cached)
        for (int i = tid; i < cnt * 64; i += 256)
            hc[i] = hR[start * 64 + i] + hA[start * 64 + i];
    __syncthreads();
    const float2* h2c = (const float2*)hc;
    const float2* hR2 = (const float2*)hR;
    const float2* hA2 = (const float2*)hA;

    for (int it = 0; it < S2SI; it++) {
        for (int g = 0; g < 32; g++) {
            int jj = warp * 32 + g;
            float p = W_ih[jj * 128 + lane]      * qs_s[lane]
                    + W_ih[jj * 128 + 32 + lane] * qs_s[32 + lane]
                    + W_ih[jj * 128 + 64 + lane] * qs_s[64 + lane]
                    + W_ih[jj * 128 + 96 + lane] * qs_s[96 + lane]
                    + W_hh[jj * 64 + lane]       * hx_s[lane]
                    + W_hh[jj * 64 + 32 + lane]  * hx_s[32 + lane];
#pragma unroll
            for (int o = 16; o > 0; o >>= 1) p += __shfl_xor_sync(0xffffffffu, p, o);
            if (lane == 0) gates_s[jj] = p + b_ih[jj] + b_hh[jj];
        }
        __syncthreads();
        if (tid < 64) {
            float ig = gates_s[tid], fg = gates_s[64 + tid], gg = gates_s[128 + tid], og = gates_s[192 + tid];
            float si = 1.f / (1.f + expf(-ig));
            float sf = 1.f / (1.f + expf(-fg));
            float so = 1.f / (1.f + expf(-og));
            float c = sf * cx_s[tid] + si * tanhf(gg);
            float hn = so * tanhf(c);
            cx_s[tid] = c; hx_s[tid] = hn; q_s[tid] = hn;
        } else if (tid < 128) {
            r_s[tid - 64] = 0.f;
        }
        __syncthreads();
        float qx = q_s[2 * lane], qy = q_s[2 * lane + 1];

        float mloc = -INFINITY;
        for (int i = warp; i < cnt; i += 8) {
            float2 hv;
            if (cached) hv = h2c[i * 32 + lane];
            else { hv = hR2[(start + i) * 32 + lane]; float2 av = hA2[(start + i) * 32 + lane]; hv.x += av.x; hv.y += av.y; }
            float p = hv.x * qx + hv.y * qy;
#pragma unroll
            for (int o = 16; o > 0; o >>= 1) p += __shfl_xor_sync(0xffffffffu, p, o);
            if (lane == 0) { if (cached) e_s[i] = p; else g_e[start + i] = p; }
            mloc = fmaxf(mloc, p);
        }
        if (lane == 0) wred[warp] = mloc;
        __syncthreads();
        if (tid == 0) {
            float m = wred[0];
            for (int i = 1; i < 8; i++) m = fmaxf(m, wred[i]);
            m_sh = m;
        }
        __syncthreads();
        float m = m_sh;

        float sloc = 0.f;
        for (int i = tid; i < cnt; i += 256) {
            float a = expf((cached ? e_s[i] : g_e[start + i]) - m);
            if (cached) e_s[i] = a; else g_e[start + i] = a;
            sloc += a;
        }
#pragma unroll
        for (int o = 16; o > 0; o >>= 1) sloc += __shfl_xor_sync(0xffffffffu, sloc, o);
        if (lane == 0) wred[warp] = sloc;
        __syncthreads();
        if (tid == 0) {
            float d = 0.f;
            for (int i = 0; i < 8; i++) d += wred[i];
            dinv_sh = (d == 0.f) ? 1.f : 1.f / d;
        }
        __syncthreads();
        float dinv = dinv_sh;

        float rx = 0.f, ry = 0.f;
        for (int i = warp; i < cnt; i += 8) {
            float a = cached ? e_s[i] : g_e[start + i];
            float2 hv;
            if (cached) hv = h2c[i * 32 + lane];
            else { hv = hR2[(start + i) * 32 + lane]; float2 av = hA2[(start + i) * 32 + lane]; hv.x += av.x; hv.y += av.y; }
            rx = fmaf(a, hv.x, rx);
            ry = fmaf(a, hv.y, ry);
        }
        atomicAdd(&r_s[2 * lane], rx * dinv);
        atomicAdd(&r_s[2 * lane + 1], ry * dinv);
        __syncthreads();
        if (tid < 64) qs_s[tid] = q_s[tid];
        else if (tid < 128) qs_s[tid] = r_s[tid - 64];
        __syncthreads();
    }

    if (tid < 64) {
        float acc = b_o1[tid];
#pragma unroll 8
        for (int k = 0; k < 128; k++)
            acc = fmaf(qs_s[k], W_o1[k * 64 + tid], acc);
        acc = fmaxf(acc, 0.f);
        red_s[tid] = acc * W_o2[tid];
    }
    __syncthreads();
    if (tid < 32) {
        float v = red_s[tid] + red_s[tid + 32];
#pragma unroll
        for (int o = 16; o > 0; o >>= 1) v += __shfl_xor_sync(0xffffffffu, v, o);
        if (tid == 0) out[b] = v + b_o2[0];
    }
}

// ================= launch =================
extern "C" void kernel_launch(void* const* d_in, const int* in_sizes, int n_in,
                              void* d_out, int out_size) {
    const float* node_feat = (const float*)d_in[0];
    const int*   node_type = (const int*)d_in[1];
    const int*   edge_index = (const int*)d_in[2];
    const int*   edge_type = (const int*)d_in[3];
    const int*   batch = (const int*)d_in[4];
    const float* W_emb = (const float*)d_in[5];
    const float* b_emb = (const float*)d_in[6];
    const float* W_e1 = (const float*)d_in[7];
    const float* b_e1 = (const float*)d_in[8];
    const float* W_e2 = (const float*)d_in[9];
    const float* b_e2 = (const float*)d_in[10];
    const float* roots = (const float*)d_in[11];
    const float* conv_bias = (const float*)d_in[12];
    const float* W_ih = (const float*)d_in[13];
    const float* W_hh = (const float*)d_in[14];
    const float* b_ih = (const float*)d_in[15];
    const float* b_hh = (const float*)d_in[16];
    const float* W_o1 = (const float*)d_in[17];
    const float* b_o1 = (const float*)d_in[18];
    const float* W_o2 = (const float*)d_in[19];
    const float* b_o2 = (const float*)d_in[20];
    float* out = (float*)d_out;

    float *h0, *h1, *aacc;
    cudaGetSymbolAddress((void**)&h0, g_h0);
    cudaGetSymbolAddress((void**)&h1, g_h1);
    cudaGetSymbolAddress((void**)&aacc, g_a);

    const int MP_SMEM = (4096 + 8 * 2048) * 4;   // 81920
    cudaFuncSetAttribute(k_mp, cudaFuncAttributeMaxDynamicSharedMemorySize, MP_SMEM);
    cudaFuncSetAttribute(k_s2s_all, cudaFuncAttributeMaxDynamicSharedMemorySize, HCAP * 64 * 4);

    k_prep<<<PB_EM + PB_EMB + PB_HIST + PB_ZERO, 256>>>(
        node_feat, node_type, W_emb, b_emb, W_e1, b_e1, W_e2, b_e2, edge_type);
    k_scat<<<PB_HIST, 256>>>(edge_index, edge_type);

    // iter 0: R0=h0 (embed), no acc; writes R1=h1, A1=aacc
    k_mp<<<NB_ROOT + NB_EDGE, 256, MP_SMEM>>>(h0, aacc, h1, aacc, roots, conv_bias, 0);
    // iter 1: reads h1 + A1; writes R2=h0, A2=aacc+NN*HH
    k_mp<<<NB_ROOT + NB_EDGE, 256, MP_SMEM>>>(h1, aacc, h0, aacc + NN * HH,
                                              roots + 4096, conv_bias + 64, 1);
    // iter 2: reads h0 + A2; writes R3=h1, A3=aacc+2*NN*HH
    k_mp<<<NB_ROOT + NB_EDGE, 256, MP_SMEM>>>(h0, aacc + NN * HH, h1, aacc + 2 * NN * HH,
                                              roots + 2 * 4096, conv_bias + 128, 1);

    k_s2s_all<<<BB, 256, HCAP * 64 * 4>>>(h1, aacc + 2 * NN * HH, batch,
                                          W_ih, W_hh, b_ih, b_hh,
                                          W_o1, b_o1, W_o2, b_o2, out);
}